// round 13
// baseline (speedup 1.0000x reference)
#include <cuda_runtime.h>
#include <cuda_fp16.h>
#include <math.h>

// ---------------------------------------------------------------------------
// STGCN: 2x (temporal conv -> clip -> InstanceNorm -> ReLU -> GCN) -> linear -> mean_T
// T=10, N=10000, E=320000, C_IN=16, C_HID=32, C_OUT=16
// Pipeline: [conv1] || [expdeg_scan -> fill]  ->  agg1+conv2  ->  agg2(2 nodes/warp)+head
// ---------------------------------------------------------------------------

#define TT 10
#define NN 10000
#define EE 320000
#define CH 32
#define COUT 16
#define TC (TT * CH)        // 320 features per node
#define E4 (EE / 4)         // 80000
#define NBLK ((E4 + 255) / 256)      // 313  (fill grid)
#define NBLK2 ((E4 + 1023) / 1024)   // 79   (expdeg grid)

// ------------------------- device scratch (no allocs allowed) ---------------
__device__ __half g_hw1[NN * TC];    // layer-1 h@gw fp16, [node][t*32+c]
__device__ __half g_hw2[NN * TC];    // layer-2 h@gw fp16, [node][t*32+c]
__device__ float  g_ewn [EE];        // raw exp(w)
__device__ int2   g_adj2[EE];        // CSR (by destination): {src, norm bits}
__device__ int    g_rowptr[NN + 1];
__device__ int    g_cnt [NN];        // re-zeroed by fill tail
__device__ int    g_fill[NN];        // write cursor (init = rowptr by scan)
__device__ float  g_deg [NN];        // re-zeroed by fill tail
__device__ float  g_dinv[NN];
__device__ float  g_partial[NBLK2];
__device__ float  g_inv_sumexp;
__device__ unsigned int g_done;      // last-block ticket (reset each pass)

// ---- fused one-kernel prep: exp(w) + partial sums + deg/cnt atomics; the
//      LAST block then computes inv_sumexp, rowptr scan (+fill cursor), dinv --
__global__ void __launch_bounds__(1024)
expdeg_scan_kernel(const float4* __restrict__ w,
                   float4* __restrict__ ewn4,
                   const int4* __restrict__ col4)
{
    __shared__ float sm[1024];
    __shared__ int   ssum[1024];
    __shared__ int   s_last;

    int tid = threadIdx.x;
    int i = blockIdx.x * 1024 + tid;
    float s = 0.f;
    if (i < E4) {
        float4 a = w[i];
        float4 e;
        e.x = expf(a.x); e.y = expf(a.y); e.z = expf(a.z); e.w = expf(a.w);
        ewn4[i] = e;
        s = e.x + e.y + e.z + e.w;
        int4 c = col4[i];
        atomicAdd(&g_deg[c.x], e.x); atomicAdd(&g_cnt[c.x], 1);
        atomicAdd(&g_deg[c.y], e.y); atomicAdd(&g_cnt[c.y], 1);
        atomicAdd(&g_deg[c.z], e.z); atomicAdd(&g_cnt[c.z], 1);
        atomicAdd(&g_deg[c.w], e.w); atomicAdd(&g_cnt[c.w], 1);
    }
    sm[tid] = s;
    __syncthreads();
    for (int o = 512; o > 0; o >>= 1) {
        if (tid < o) sm[tid] += sm[tid + o];
        __syncthreads();
    }
    if (tid == 0) g_partial[blockIdx.x] = sm[0];
    __threadfence();
    if (tid == 0) s_last = (atomicAdd(&g_done, 1) == gridDim.x - 1);
    __syncthreads();
    if (!s_last) return;

    // ---- last block: finish everything ----
    if (tid == 0) g_done = 0;       // reset ticket for next call
    __threadfence();

    sm[tid] = (tid < NBLK2) ? g_partial[tid] : 0.f;
    __syncthreads();
    for (int o = 512; o > 0; o >>= 1) {
        if (tid < o) sm[tid] += sm[tid + o];
        __syncthreads();
    }
    float inv = 1.f / sm[0];
    if (tid == 0) g_inv_sumexp = inv;

    const int CHK = (NN + 1023) / 1024;   // 10
    int local[CHK];
    int base = tid * CHK;
    int acc = 0;
#pragma unroll
    for (int k = 0; k < CHK; k++) {
        int idx = base + k;
        local[k] = (idx < NN) ? g_cnt[idx] : 0;
        acc += local[k];
    }
    ssum[tid] = acc;
    __syncthreads();
    for (int off = 1; off < 1024; off <<= 1) {
        int v = (tid >= off) ? ssum[tid - off] : 0;
        __syncthreads();
        ssum[tid] += v;
        __syncthreads();
    }
    int ex = ssum[tid] - acc;
#pragma unroll
    for (int k = 0; k < CHK; k++) {
        int idx = base + k;
        if (idx < NN) { g_rowptr[idx] = ex; g_fill[idx] = ex; }
        ex += local[k];
    }
    if (tid == 1023) g_rowptr[NN] = ssum[1023];
    for (int idx = tid; idx < NN; idx += 1024)
        g_dinv[idx] = rsqrtf(inv * g_deg[idx] + 1.0f);
}

// ---- CSR fill, 4 edges/thread; tail re-zeros cnt/deg for next call ----------
__global__ void fill_kernel(const int4* __restrict__ row4, const int4* __restrict__ col4,
                            const float4* __restrict__ ewn4) {
    int i = blockIdx.x * blockDim.x + threadIdx.x;
    if (i < E4) {
        int4   c = col4[i];
        int4   r = row4[i];
        float4 w = ewn4[i];
        float inv = g_inv_sumexp;
        int p0 = atomicAdd(&g_fill[c.x], 1);
        int p1 = atomicAdd(&g_fill[c.y], 1);
        int p2 = atomicAdd(&g_fill[c.z], 1);
        int p3 = atomicAdd(&g_fill[c.w], 1);
        float n0 = g_dinv[r.x] * (w.x * inv) * g_dinv[c.x];
        float n1 = g_dinv[r.y] * (w.y * inv) * g_dinv[c.y];
        float n2 = g_dinv[r.z] * (w.z * inv) * g_dinv[c.z];
        float n3 = g_dinv[r.w] * (w.w * inv) * g_dinv[c.w];
        g_adj2[p0] = make_int2(r.x, __float_as_int(n0));
        g_adj2[p1] = make_int2(r.y, __float_as_int(n1));
        g_adj2[p2] = make_int2(r.z, __float_as_int(n2));
        g_adj2[p3] = make_int2(r.w, __float_as_int(n3));
    }
    if (i < NN) { g_cnt[i] = 0; g_deg[i] = 0.f; }
}

// ------------------- layer-1: temporal conv + IN + relu + (h @ gw) ----------
__global__ void __launch_bounds__(256)
conv1_kernel(const float* __restrict__ x,
             const float* __restrict__ tw, const float* __restrict__ tb,
             const float* __restrict__ gamma, const float* __restrict__ beta,
             const float* __restrict__ gw, __half* __restrict__ hw_out)
{
    const int CIN = 16;
    const int NPB = 8;
    const int TP = 12;
    __shared__ float xh[NPB][CH][TP];      // union: x rows [0,CIN), then h rows [0,32)
    __shared__ float4 tws4[CH][CIN + 1];   // (w0,w1,w2,_), ODD row stride: no conflicts
    __shared__ float gws[CH][CH];

    int tid = threadIdx.x;
    int nodeBase = blockIdx.x * NPB;

    for (int i = tid; i < NPB * TT * CIN; i += 256) {
        int ln = i / (TT * CIN);
        int r  = i % (TT * CIN);
        int t  = r / CIN;
        int ci = r % CIN;
        long gn = nodeBase + ln;
        xh[ln][ci][t] = x[(long)t * (NN * CIN) + gn * CIN + ci];
    }
    for (int i = tid; i < CH * CIN; i += 256) {
        int c  = i / CIN;
        int ci = i % CIN;
        const float* p = &tw[(c * CIN + ci) * 3];
        tws4[c][ci] = make_float4(p[0], p[1], p[2], 0.f);
    }
    for (int i = tid; i < CH * CH; i += 256)
        gws[i / CH][i % CH] = gw[i];
    __syncthreads();

    int ln = tid >> 5;
    int c  = tid & 31;
    float bias = tb[c], ga = gamma[c], be = beta[c];

    float y[TT];
#pragma unroll
    for (int t = 0; t < TT; t++) y[t] = bias;

#pragma unroll 4
    for (int ci = 0; ci < CIN; ci++) {
        float4 W = tws4[c][ci];
        float4 A = *(const float4*)&xh[ln][ci][0];
        float4 B = *(const float4*)&xh[ln][ci][4];
        float2 C2 = *(const float2*)&xh[ln][ci][8];
        float xv[10] = {A.x, A.y, A.z, A.w, B.x, B.y, B.z, B.w, C2.x, C2.y};
#pragma unroll
        for (int t = 0; t < TT; t++) {
            float a = y[t];
            if (t > 0)      a = fmaf(W.x, xv[t - 1], a);
            a = fmaf(W.y, xv[t], a);
            if (t < TT - 1) a = fmaf(W.z, xv[t + 1], a);
            y[t] = a;
        }
    }
#pragma unroll
    for (int t = 0; t < TT; t++) y[t] = fminf(fmaxf(y[t], -10.f), 10.f);

    float mu = 0.f;
#pragma unroll
    for (int t = 0; t < TT; t++) mu += y[t];
    mu *= 0.1f;
    float var = 0.f;
#pragma unroll
    for (int t = 0; t < TT; t++) { float d = y[t] - mu; var += d * d; }
    var *= 0.1f;
    float sc = ga * rsqrtf(var + 1e-5f);
#pragma unroll
    for (int t = 0; t < TT; t++)
        y[t] = fmaxf((y[t] - mu) * sc + be, 0.f);

    __syncwarp();
    *(float4*)&xh[ln][c][0] = make_float4(y[0], y[1], y[2], y[3]);
    *(float4*)&xh[ln][c][4] = make_float4(y[4], y[5], y[6], y[7]);
    *(float2*)&xh[ln][c][8] = make_float2(y[8], y[9]);
    __syncwarp();

    float o[TT];
#pragma unroll
    for (int t = 0; t < TT; t++) o[t] = 0.f;
#pragma unroll 4
    for (int cc = 0; cc < CH; cc++) {
        float g = gws[cc][c];
        float4 A = *(const float4*)&xh[ln][cc][0];
        float4 B = *(const float4*)&xh[ln][cc][4];
        float2 C2 = *(const float2*)&xh[ln][cc][8];
        o[0] = fmaf(g, A.x, o[0]); o[1] = fmaf(g, A.y, o[1]);
        o[2] = fmaf(g, A.z, o[2]); o[3] = fmaf(g, A.w, o[3]);
        o[4] = fmaf(g, B.x, o[4]); o[5] = fmaf(g, B.y, o[5]);
        o[6] = fmaf(g, B.z, o[6]); o[7] = fmaf(g, B.w, o[7]);
        o[8] = fmaf(g, C2.x, o[8]); o[9] = fmaf(g, C2.y, o[9]);
    }

    long gn = nodeBase + ln;
#pragma unroll
    for (int t = 0; t < TT; t++)
        hw_out[gn * TC + t * CH + c] = __float2half(o[t]);
}

// ---- one group of 4 edges: 4 full-width main passes + 1 full-width remainder
// pass (lane handles uint4[32+(lane&7)] of edge j0+(lane>>3)). Padding edges
// have nm=0 / src=0, so processing a full group is always safe. --------------
__device__ __forceinline__ void edge_group4(
    const __half* __restrict__ hw, int2 d, int j0, int lane, int lg, int lu,
    float acc0[8], float acc1[8])
{
#pragma unroll
    for (int u = 0; u < 4; u++) {
        int j = j0 + u;
        int   src = __shfl_sync(0xffffffff, d.x, j);
        float nm  = __int_as_float(__shfl_sync(0xffffffff, d.y, j));
        const uint4* p = (const uint4*)(hw + (size_t)src * TC);
        uint4 uu = __ldg(&p[lane]);
        float2 f0 = __half22float2(*(const __half2*)&uu.x);
        float2 f1 = __half22float2(*(const __half2*)&uu.y);
        float2 f2 = __half22float2(*(const __half2*)&uu.z);
        float2 f3 = __half22float2(*(const __half2*)&uu.w);
        acc0[0] = fmaf(nm, f0.x, acc0[0]); acc0[1] = fmaf(nm, f0.y, acc0[1]);
        acc0[2] = fmaf(nm, f1.x, acc0[2]); acc0[3] = fmaf(nm, f1.y, acc0[3]);
        acc0[4] = fmaf(nm, f2.x, acc0[4]); acc0[5] = fmaf(nm, f2.y, acc0[5]);
        acc0[6] = fmaf(nm, f3.x, acc0[6]); acc0[7] = fmaf(nm, f3.y, acc0[7]);
    }
    int jr = j0 + lg;
    int   srcr = __shfl_sync(0xffffffff, d.x, jr);
    float nmr  = __int_as_float(__shfl_sync(0xffffffff, d.y, jr));
    const uint4* pr = (const uint4*)(hw + (size_t)srcr * TC);
    uint4 vv = __ldg(&pr[32 + lu]);
    float2 g0 = __half22float2(*(const __half2*)&vv.x);
    float2 g1 = __half22float2(*(const __half2*)&vv.y);
    float2 g2 = __half22float2(*(const __half2*)&vv.z);
    float2 g3 = __half22float2(*(const __half2*)&vv.w);
    acc1[0] = fmaf(nmr, g0.x, acc1[0]); acc1[1] = fmaf(nmr, g0.y, acc1[1]);
    acc1[2] = fmaf(nmr, g1.x, acc1[2]); acc1[3] = fmaf(nmr, g1.y, acc1[3]);
    acc1[4] = fmaf(nmr, g2.x, acc1[4]); acc1[5] = fmaf(nmr, g2.y, acc1[5]);
    acc1[6] = fmaf(nmr, g3.x, acc1[6]); acc1[7] = fmaf(nmr, g3.y, acc1[7]);
}

// ---- butterfly-reduce acc1, add self-loop, bias/relu/clip -------------------
__device__ __forceinline__ void finish_node(
    const __half* __restrict__ hw, int node, int lane,
    const float* __restrict__ gb, float acc0[8], float acc1[8])
{
#pragma unroll
    for (int k = 0; k < 8; k++) {
        acc1[k] += __shfl_xor_sync(0xffffffff, acc1[k], 8);
        acc1[k] += __shfl_xor_sync(0xffffffff, acc1[k], 16);
    }
    float di = g_dinv[node];
    float w  = di * di;
    const uint4* p = (const uint4*)(hw + (size_t)node * TC);
    uint4 u = __ldg(&p[lane]);
    float2 f0 = __half22float2(*(const __half2*)&u.x);
    float2 f1 = __half22float2(*(const __half2*)&u.y);
    float2 f2 = __half22float2(*(const __half2*)&u.z);
    float2 f3 = __half22float2(*(const __half2*)&u.w);
    acc0[0] = fmaf(w, f0.x, acc0[0]); acc0[1] = fmaf(w, f0.y, acc0[1]);
    acc0[2] = fmaf(w, f1.x, acc0[2]); acc0[3] = fmaf(w, f1.y, acc0[3]);
    acc0[4] = fmaf(w, f2.x, acc0[4]); acc0[5] = fmaf(w, f2.y, acc0[5]);
    acc0[6] = fmaf(w, f3.x, acc0[6]); acc0[7] = fmaf(w, f3.y, acc0[7]);
    if (lane < 8) {
        uint4 v = __ldg(&p[32 + lane]);
        float2 g0 = __half22float2(*(const __half2*)&v.x);
        float2 g1 = __half22float2(*(const __half2*)&v.y);
        float2 g2 = __half22float2(*(const __half2*)&v.z);
        float2 g3 = __half22float2(*(const __half2*)&v.w);
        acc1[0] = fmaf(w, g0.x, acc1[0]); acc1[1] = fmaf(w, g0.y, acc1[1]);
        acc1[2] = fmaf(w, g1.x, acc1[2]); acc1[3] = fmaf(w, g1.y, acc1[3]);
        acc1[4] = fmaf(w, g2.x, acc1[4]); acc1[5] = fmaf(w, g2.y, acc1[5]);
        acc1[6] = fmaf(w, g3.x, acc1[6]); acc1[7] = fmaf(w, g3.y, acc1[7]);
    }
    int c0 = (8 * lane) & 31;
    float4 b0 = *(const float4*)&gb[c0];
    float4 b1 = *(const float4*)&gb[c0 + 4];
    acc0[0] = fminf(fmaxf(acc0[0] + b0.x, 0.f), 10.f);
    acc0[1] = fminf(fmaxf(acc0[1] + b0.y, 0.f), 10.f);
    acc0[2] = fminf(fmaxf(acc0[2] + b0.z, 0.f), 10.f);
    acc0[3] = fminf(fmaxf(acc0[3] + b0.w, 0.f), 10.f);
    acc0[4] = fminf(fmaxf(acc0[4] + b1.x, 0.f), 10.f);
    acc0[5] = fminf(fmaxf(acc0[5] + b1.y, 0.f), 10.f);
    acc0[6] = fminf(fmaxf(acc0[6] + b1.z, 0.f), 10.f);
    acc0[7] = fminf(fmaxf(acc0[7] + b1.w, 0.f), 10.f);
    if (lane < 8) {
        acc1[0] = fminf(fmaxf(acc1[0] + b0.x, 0.f), 10.f);
        acc1[1] = fminf(fmaxf(acc1[1] + b0.y, 0.f), 10.f);
        acc1[2] = fminf(fmaxf(acc1[2] + b0.z, 0.f), 10.f);
        acc1[3] = fminf(fmaxf(acc1[3] + b0.w, 0.f), 10.f);
        acc1[4] = fminf(fmaxf(acc1[4] + b1.x, 0.f), 10.f);
        acc1[5] = fminf(fmaxf(acc1[5] + b1.y, 0.f), 10.f);
        acc1[6] = fminf(fmaxf(acc1[6] + b1.z, 0.f), 10.f);
        acc1[7] = fminf(fmaxf(acc1[7] + b1.w, 0.f), 10.f);
    }
}

// ---- single-node gather with descriptor double-buffering --------------------
__device__ __forceinline__ void gather_node(
    const __half* __restrict__ hw, int node, int lane,
    const float* __restrict__ gb, float acc0[8], float acc1[8])
{
#pragma unroll
    for (int k = 0; k < 8; k++) { acc0[k] = 0.f; acc1[k] = 0.f; }

    int s = g_rowptr[node];
    int e = g_rowptr[node + 1];
    int lg = lane >> 3;
    int lu = lane & 7;

    int base = s;
    int2 d = make_int2(0, 0);
    if (base + lane < e) d = g_adj2[base + lane];

    while (base < e) {
        int nbase = base + 32;
        int2 dn = make_int2(0, 0);
        if (nbase + lane < e) dn = g_adj2[nbase + lane];   // prefetch next block
        int cnt = min(32, e - base);
#pragma unroll 2
        for (int j0 = 0; j0 < cnt; j0 += 4)
            edge_group4(hw, d, j0, lane, lg, lu, acc0, acc1);
        d = dn;
        base = nbase;
    }

    finish_node(hw, node, lane, gb, acc0, acc1);
}

// ---- two-node interleaved gather (doubles per-warp LDG streams) -------------
__device__ __forceinline__ void gather_node2(
    const __half* __restrict__ hw, int nA, int nB, int lane,
    const float* __restrict__ gb,
    float aA0[8], float aA1[8], float aB0[8], float aB1[8])
{
#pragma unroll
    for (int k = 0; k < 8; k++) { aA0[k] = 0.f; aA1[k] = 0.f; aB0[k] = 0.f; aB1[k] = 0.f; }

    int sA = g_rowptr[nA], eA = g_rowptr[nA + 1];
    int sB = g_rowptr[nB], eB = g_rowptr[nB + 1];
    int lg = lane >> 3;
    int lu = lane & 7;

    int baseA = sA, baseB = sB;
    int2 dA = make_int2(0, 0), dB = make_int2(0, 0);
    if (baseA + lane < eA) dA = g_adj2[baseA + lane];
    if (baseB + lane < eB) dB = g_adj2[baseB + lane];

    while (baseA < eA || baseB < eB) {
        int2 dAn = make_int2(0, 0), dBn = make_int2(0, 0);
        if (baseA + 32 + lane < eA) dAn = g_adj2[baseA + 32 + lane];
        if (baseB + 32 + lane < eB) dBn = g_adj2[baseB + 32 + lane];
        int cntA = (baseA < eA) ? min(32, eA - baseA) : 0;
        int cntB = (baseB < eB) ? min(32, eB - baseB) : 0;
        int maxc = max(cntA, cntB);
        for (int j0 = 0; j0 < maxc; j0 += 4) {
            if (j0 < cntA) edge_group4(hw, dA, j0, lane, lg, lu, aA0, aA1);
            if (j0 < cntB) edge_group4(hw, dB, j0, lane, lg, lu, aB0, aB1);
        }
        dA = dAn; dB = dBn;
        baseA += 32; baseB += 32;
    }

    finish_node(hw, nA, lane, gb, aA0, aA1);
    finish_node(hw, nB, lane, gb, aB0, aB1);
}

// ------------ FUSED layer-1 aggregate + layer-2 conv/IN/relu/(h@gw) ----------
__global__ void __launch_bounds__(256, 5)
agg1_conv2_kernel(const __half* __restrict__ hw1,
                  const float* __restrict__ gb1,
                  const float* __restrict__ tw2, const float* __restrict__ tb2,
                  const float* __restrict__ gamma2, const float* __restrict__ beta2,
                  const float* __restrict__ gw2,
                  __half* __restrict__ hw2)
{
    const int TP = 12;
    __shared__ float s_xh[8][CH * TP];        // per-warp [c][t] tile (union x/h)
    __shared__ float4 tws4[CH][CH + 1];       // (w0,w1,w2,_), ODD row stride
    __shared__ float gws[CH][CH];

    int tid  = threadIdx.x;
    int warp = tid >> 5;
    int lane = tid & 31;
    int node = blockIdx.x * 8 + warp;

    for (int i = tid; i < CH * CH; i += 256) {
        int c  = i / CH;
        int ci = i % CH;
        const float* p = &tw2[(c * CH + ci) * 3];
        tws4[c][ci] = make_float4(p[0], p[1], p[2], 0.f);
    }
    for (int i = tid; i < CH * CH; i += 256)
        gws[i / CH][i % CH] = gw2[i];
    __syncthreads();

    float acc0[8], acc1[8];
    gather_node(hw1, node, lane, gb1, acc0, acc1);

    float* X = s_xh[warp];
#pragma unroll
    for (int k = 0; k < 8; k++) {
        int e = 8 * lane + k;
        X[(e & 31) * TP + (e >> 5)] = acc0[k];
    }
    if (lane < 8) {
#pragma unroll
        for (int k = 0; k < 8; k++) {
            int e = 256 + 8 * lane + k;
            X[(e & 31) * TP + (e >> 5)] = acc1[k];
        }
    }
    __syncwarp();

    int c = lane;
    float y[TT];
    float bias = tb2[c], ga = gamma2[c], be = beta2[c];
#pragma unroll
    for (int t = 0; t < TT; t++) y[t] = bias;
#pragma unroll 4
    for (int ci = 0; ci < CH; ci++) {
        float4 W = tws4[c][ci];
        float4 A = *(const float4*)&X[ci * TP + 0];
        float4 B = *(const float4*)&X[ci * TP + 4];
        float2 C2 = *(const float2*)&X[ci * TP + 8];
        float xv[10] = {A.x, A.y, A.z, A.w, B.x, B.y, B.z, B.w, C2.x, C2.y};
#pragma unroll
        for (int t = 0; t < TT; t++) {
            float a = y[t];
            if (t > 0)      a = fmaf(W.x, xv[t - 1], a);
            a = fmaf(W.y, xv[t], a);
            if (t < TT - 1) a = fmaf(W.z, xv[t + 1], a);
            y[t] = a;
        }
    }
#pragma unroll
    for (int t = 0; t < TT; t++) y[t] = fminf(fmaxf(y[t], -10.f), 10.f);

    float mu = 0.f;
#pragma unroll
    for (int t = 0; t < TT; t++) mu += y[t];
    mu *= 0.1f;
    float var = 0.f;
#pragma unroll
    for (int t = 0; t < TT; t++) { float d = y[t] - mu; var += d * d; }
    var *= 0.1f;
    float sc = ga * rsqrtf(var + 1e-5f);
#pragma unroll
    for (int t = 0; t < TT; t++)
        y[t] = fmaxf((y[t] - mu) * sc + be, 0.f);

    __syncwarp();
    *(float4*)&X[c * TP + 0] = make_float4(y[0], y[1], y[2], y[3]);
    *(float4*)&X[c * TP + 4] = make_float4(y[4], y[5], y[6], y[7]);
    *(float2*)&X[c * TP + 8] = make_float2(y[8], y[9]);
    __syncwarp();

    float o[TT];
#pragma unroll
    for (int t = 0; t < TT; t++) o[t] = 0.f;
#pragma unroll 4
    for (int cc = 0; cc < CH; cc++) {
        float g = gws[cc][c];
        float4 A = *(const float4*)&X[cc * TP + 0];
        float4 B = *(const float4*)&X[cc * TP + 4];
        float2 C2 = *(const float2*)&X[cc * TP + 8];
        o[0] = fmaf(g, A.x, o[0]); o[1] = fmaf(g, A.y, o[1]);
        o[2] = fmaf(g, A.z, o[2]); o[3] = fmaf(g, A.w, o[3]);
        o[4] = fmaf(g, B.x, o[4]); o[5] = fmaf(g, B.y, o[5]);
        o[6] = fmaf(g, B.z, o[6]); o[7] = fmaf(g, B.w, o[7]);
        o[8] = fmaf(g, C2.x, o[8]); o[9] = fmaf(g, C2.y, o[9]);
    }

    long gn = node;
#pragma unroll
    for (int t = 0; t < TT; t++)
        hw2[gn * TC + t * CH + c] = __float2half(o[t]);
}

// ------------ layer-2 aggregate (2 nodes/warp) + mean-over-T + linear --------
__global__ void __launch_bounds__(256)
agg2_head_kernel(const __half* __restrict__ hw,
                 const float* __restrict__ gb,
                 float* __restrict__ out,
                 const float* __restrict__ ow,
                 const float* __restrict__ ob)
{
    __shared__ float s_feat[8][TC];
    __shared__ float s_m[8][CH];

    int warp = threadIdx.x >> 5;
    int lane = threadIdx.x & 31;
    int nA = blockIdx.x * 16 + warp * 2;   // NN % 16 == 0
    int nB = nA + 1;

    float aA0[8], aA1[8], aB0[8], aB1[8];
    gather_node2(hw, nA, nB, lane, gb, aA0, aA1, aB0, aB1);

    // ---- head for node A ----
    *(float4*)&s_feat[warp][8 * lane]     = make_float4(aA0[0], aA0[1], aA0[2], aA0[3]);
    *(float4*)&s_feat[warp][8 * lane + 4] = make_float4(aA0[4], aA0[5], aA0[6], aA0[7]);
    if (lane < 8) {
        *(float4*)&s_feat[warp][256 + 8 * lane]     = make_float4(aA1[0], aA1[1], aA1[2], aA1[3]);
        *(float4*)&s_feat[warp][256 + 8 * lane + 4] = make_float4(aA1[4], aA1[5], aA1[6], aA1[7]);
    }
    __syncwarp();
    float mA = 0.f;
#pragma unroll
    for (int t = 0; t < TT; t++) mA += s_feat[warp][t * CH + lane];
    s_m[warp][lane] = mA * 0.1f;
    __syncwarp();
    if (lane < COUT) {
        float o = ob[lane];
#pragma unroll
        for (int cc = 0; cc < CH; cc++)
            o = fmaf(s_m[warp][cc], __ldg(&ow[cc * COUT + lane]), o);
        out[(size_t)nA * COUT + lane] = o;
    }
    __syncwarp();

    // ---- head for node B ----
    *(float4*)&s_feat[warp][8 * lane]     = make_float4(aB0[0], aB0[1], aB0[2], aB0[3]);
    *(float4*)&s_feat[warp][8 * lane + 4] = make_float4(aB0[4], aB0[5], aB0[6], aB0[7]);
    if (lane < 8) {
        *(float4*)&s_feat[warp][256 + 8 * lane]     = make_float4(aB1[0], aB1[1], aB1[2], aB1[3]);
        *(float4*)&s_feat[warp][256 + 8 * lane + 4] = make_float4(aB1[4], aB1[5], aB1[6], aB1[7]);
    }
    __syncwarp();
    float mB = 0.f;
#pragma unroll
    for (int t = 0; t < TT; t++) mB += s_feat[warp][t * CH + lane];
    s_m[warp][lane] = mB * 0.1f;
    __syncwarp();
    if (lane < COUT) {
        float o = ob[lane];
#pragma unroll
        for (int cc = 0; cc < CH; cc++)
            o = fmaf(s_m[warp][cc], __ldg(&ow[cc * COUT + lane]), o);
        out[(size_t)nB * COUT + lane] = o;
    }
}

// ---------------------------------------------------------------------------
extern "C" void kernel_launch(void* const* d_in, const int* in_sizes, int n_in,
                              void* d_out, int out_size)
{
    const float* x   = (const float*)d_in[0];
    const int*   ei  = (const int*)  d_in[1];   // [2, E]
    const float* ew  = (const float*)d_in[2];
    const float* l1_tw    = (const float*)d_in[3];
    const float* l1_tb    = (const float*)d_in[4];
    const float* l1_gw    = (const float*)d_in[5];
    const float* l1_gb    = (const float*)d_in[6];
    const float* l1_gamma = (const float*)d_in[7];
    const float* l1_beta  = (const float*)d_in[8];
    const float* l2_tw    = (const float*)d_in[9];
    const float* l2_tb    = (const float*)d_in[10];
    const float* l2_gw    = (const float*)d_in[11];
    const float* l2_gb    = (const float*)d_in[12];
    const float* l2_gamma = (const float*)d_in[13];
    const float* l2_beta  = (const float*)d_in[14];
    const float* out_w    = (const float*)d_in[15];
    const float* out_b    = (const float*)d_in[16];

    const int* e_row = ei;        // sources
    const int* e_col = ei + EE;   // destinations

    __half* hw1_ptr; cudaGetSymbolAddress((void**)&hw1_ptr, g_hw1);
    __half* hw2_ptr; cudaGetSymbolAddress((void**)&hw2_ptr, g_hw2);
    float* ewn_ptr;  cudaGetSymbolAddress((void**)&ewn_ptr, g_ewn);

    // One-time host-side resources (no device memory involved).
    static cudaStream_t s2 = nullptr;
    static cudaEvent_t evA = nullptr, evB = nullptr;
    if (s2 == nullptr) {
        cudaStreamCreateWithFlags(&s2, cudaStreamNonBlocking);
        cudaEventCreateWithFlags(&evA, cudaEventDisableTiming);
        cudaEventCreateWithFlags(&evB, cudaEventDisableTiming);
    }

    // fork: graph-prep chain on s2, conv1 on the origin stream
    cudaEventRecord(evA, 0);
    cudaStreamWaitEvent(s2, evA, 0);

    expdeg_scan_kernel<<<NBLK2, 1024, 0, s2>>>(
        (const float4*)ew, (float4*)ewn_ptr, (const int4*)e_col);
    fill_kernel<<<NBLK, 256, 0, s2>>>(
        (const int4*)e_row, (const int4*)e_col, (const float4*)ewn_ptr);
    cudaEventRecord(evB, s2);

    conv1_kernel<<<NN / 8, 256>>>(
        x, l1_tw, l1_tb, l1_gamma, l1_beta, l1_gw, hw1_ptr);

    // join: aggregates need both conv1 output and the CSR
    cudaStreamWaitEvent(0, evB, 0);

    agg1_conv2_kernel<<<NN / 8, 256>>>(
        hw1_ptr, l1_gb, l2_tw, l2_tb, l2_gamma, l2_beta, l2_gw, hw2_ptr);
    agg2_head_kernel<<<NN / 16, 256>>>(hw2_ptr, l2_gb, (float*)d_out, out_w, out_b);
}

// round 14
// speedup vs baseline: 1.1134x; 1.1134x over previous
#include <cuda_runtime.h>
#include <cuda_fp16.h>
#include <math.h>

// ---------------------------------------------------------------------------
// STGCN: 2x (temporal conv -> clip -> InstanceNorm -> ReLU -> GCN) -> linear -> mean_T
// T=10, N=10000, E=320000, C_IN=16, C_HID=32, C_OUT=16
// Pipeline: [conv1] || [expdeg_scan -> fill]  ->  agg1+conv2  ->  agg2+head
// ---------------------------------------------------------------------------

#define TT 10
#define NN 10000
#define EE 320000
#define CH 32
#define COUT 16
#define TC (TT * CH)        // 320 features per node
#define E4 (EE / 4)         // 80000
#define NBLK ((E4 + 255) / 256)      // 313  (fill grid)
#define NBLK2 ((E4 + 1023) / 1024)   // 79   (expdeg grid)

// ------------------------- device scratch (no allocs allowed) ---------------
__device__ __half g_hw1[NN * TC];    // layer-1 h@gw fp16, [node][t*32+c]
__device__ __half g_hw2[NN * TC];    // layer-2 h@gw fp16, [node][t*32+c]
__device__ float  g_ewn [EE];        // raw exp(w)
__device__ int2   g_adj2[EE];        // CSR (by destination): {src, norm bits}
__device__ int    g_rowptr[NN + 1];
__device__ int    g_cnt [NN];        // re-zeroed by fill tail
__device__ int    g_fill[NN];        // write cursor (init = rowptr by scan)
__device__ float  g_deg [NN];        // re-zeroed by fill tail
__device__ float  g_dinv[NN];
__device__ float  g_partial[NBLK2];
__device__ float  g_inv_sumexp;
__device__ unsigned int g_done;      // last-block ticket (reset each pass)

// ---- fused one-kernel prep: exp(w) + partial sums + deg/cnt atomics; the
//      LAST block then computes inv_sumexp, rowptr scan (+fill cursor), dinv --
__global__ void __launch_bounds__(1024)
expdeg_scan_kernel(const float4* __restrict__ w,
                   float4* __restrict__ ewn4,
                   const int4* __restrict__ col4)
{
    __shared__ float sm[1024];
    __shared__ int   ssum[1024];
    __shared__ int   s_last;

    int tid = threadIdx.x;
    int i = blockIdx.x * 1024 + tid;
    float s = 0.f;
    if (i < E4) {
        float4 a = w[i];
        float4 e;
        e.x = expf(a.x); e.y = expf(a.y); e.z = expf(a.z); e.w = expf(a.w);
        ewn4[i] = e;
        s = e.x + e.y + e.z + e.w;
        int4 c = col4[i];
        atomicAdd(&g_deg[c.x], e.x); atomicAdd(&g_cnt[c.x], 1);
        atomicAdd(&g_deg[c.y], e.y); atomicAdd(&g_cnt[c.y], 1);
        atomicAdd(&g_deg[c.z], e.z); atomicAdd(&g_cnt[c.z], 1);
        atomicAdd(&g_deg[c.w], e.w); atomicAdd(&g_cnt[c.w], 1);
    }
    sm[tid] = s;
    __syncthreads();
    for (int o = 512; o > 0; o >>= 1) {
        if (tid < o) sm[tid] += sm[tid + o];
        __syncthreads();
    }
    if (tid == 0) g_partial[blockIdx.x] = sm[0];
    __threadfence();
    if (tid == 0) s_last = (atomicAdd(&g_done, 1) == gridDim.x - 1);
    __syncthreads();
    if (!s_last) return;

    // ---- last block: finish everything ----
    if (tid == 0) g_done = 0;       // reset ticket for next call
    __threadfence();

    sm[tid] = (tid < NBLK2) ? g_partial[tid] : 0.f;
    __syncthreads();
    for (int o = 512; o > 0; o >>= 1) {
        if (tid < o) sm[tid] += sm[tid + o];
        __syncthreads();
    }
    float inv = 1.f / sm[0];
    if (tid == 0) g_inv_sumexp = inv;

    const int CHK = (NN + 1023) / 1024;   // 10
    int local[CHK];
    int base = tid * CHK;
    int acc = 0;
#pragma unroll
    for (int k = 0; k < CHK; k++) {
        int idx = base + k;
        local[k] = (idx < NN) ? g_cnt[idx] : 0;
        acc += local[k];
    }
    ssum[tid] = acc;
    __syncthreads();
    for (int off = 1; off < 1024; off <<= 1) {
        int v = (tid >= off) ? ssum[tid - off] : 0;
        __syncthreads();
        ssum[tid] += v;
        __syncthreads();
    }
    int ex = ssum[tid] - acc;
#pragma unroll
    for (int k = 0; k < CHK; k++) {
        int idx = base + k;
        if (idx < NN) { g_rowptr[idx] = ex; g_fill[idx] = ex; }
        ex += local[k];
    }
    if (tid == 1023) g_rowptr[NN] = ssum[1023];
    for (int idx = tid; idx < NN; idx += 1024)
        g_dinv[idx] = rsqrtf(inv * g_deg[idx] + 1.0f);
}

// ---- CSR fill, 4 edges/thread; tail re-zeros cnt/deg for next call ----------
__global__ void fill_kernel(const int4* __restrict__ row4, const int4* __restrict__ col4,
                            const float4* __restrict__ ewn4) {
    int i = blockIdx.x * blockDim.x + threadIdx.x;
    if (i < E4) {
        int4   c = col4[i];
        int4   r = row4[i];
        float4 w = ewn4[i];
        float inv = g_inv_sumexp;
        int p0 = atomicAdd(&g_fill[c.x], 1);
        int p1 = atomicAdd(&g_fill[c.y], 1);
        int p2 = atomicAdd(&g_fill[c.z], 1);
        int p3 = atomicAdd(&g_fill[c.w], 1);
        float n0 = g_dinv[r.x] * (w.x * inv) * g_dinv[c.x];
        float n1 = g_dinv[r.y] * (w.y * inv) * g_dinv[c.y];
        float n2 = g_dinv[r.z] * (w.z * inv) * g_dinv[c.z];
        float n3 = g_dinv[r.w] * (w.w * inv) * g_dinv[c.w];
        g_adj2[p0] = make_int2(r.x, __float_as_int(n0));
        g_adj2[p1] = make_int2(r.y, __float_as_int(n1));
        g_adj2[p2] = make_int2(r.z, __float_as_int(n2));
        g_adj2[p3] = make_int2(r.w, __float_as_int(n3));
    }
    if (i < NN) { g_cnt[i] = 0; g_deg[i] = 0.f; }
}

// ------------------- layer-1: temporal conv + IN + relu + (h @ gw) ----------
__global__ void __launch_bounds__(256)
conv1_kernel(const float* __restrict__ x,
             const float* __restrict__ tw, const float* __restrict__ tb,
             const float* __restrict__ gamma, const float* __restrict__ beta,
             const float* __restrict__ gw, __half* __restrict__ hw_out)
{
    const int CIN = 16;
    const int NPB = 8;
    const int TP = 12;
    __shared__ float xh[NPB][CH][TP];      // union: x rows [0,CIN), then h rows [0,32)
    __shared__ float4 tws4[CH][CIN + 1];   // (w0,w1,w2,_), ODD row stride: no conflicts
    __shared__ float gws[CH][CH];

    int tid = threadIdx.x;
    int nodeBase = blockIdx.x * NPB;

    for (int i = tid; i < NPB * TT * CIN; i += 256) {
        int ln = i / (TT * CIN);
        int r  = i % (TT * CIN);
        int t  = r / CIN;
        int ci = r % CIN;
        long gn = nodeBase + ln;
        xh[ln][ci][t] = x[(long)t * (NN * CIN) + gn * CIN + ci];
    }
    for (int i = tid; i < CH * CIN; i += 256) {
        int c  = i / CIN;
        int ci = i % CIN;
        const float* p = &tw[(c * CIN + ci) * 3];
        tws4[c][ci] = make_float4(p[0], p[1], p[2], 0.f);
    }
    for (int i = tid; i < CH * CH; i += 256)
        gws[i / CH][i % CH] = gw[i];
    __syncthreads();

    int ln = tid >> 5;
    int c  = tid & 31;
    float bias = tb[c], ga = gamma[c], be = beta[c];

    float y[TT];
#pragma unroll
    for (int t = 0; t < TT; t++) y[t] = bias;

#pragma unroll 4
    for (int ci = 0; ci < CIN; ci++) {
        float4 W = tws4[c][ci];
        float4 A = *(const float4*)&xh[ln][ci][0];
        float4 B = *(const float4*)&xh[ln][ci][4];
        float2 C2 = *(const float2*)&xh[ln][ci][8];
        float xv[10] = {A.x, A.y, A.z, A.w, B.x, B.y, B.z, B.w, C2.x, C2.y};
#pragma unroll
        for (int t = 0; t < TT; t++) {
            float a = y[t];
            if (t > 0)      a = fmaf(W.x, xv[t - 1], a);
            a = fmaf(W.y, xv[t], a);
            if (t < TT - 1) a = fmaf(W.z, xv[t + 1], a);
            y[t] = a;
        }
    }
#pragma unroll
    for (int t = 0; t < TT; t++) y[t] = fminf(fmaxf(y[t], -10.f), 10.f);

    float mu = 0.f;
#pragma unroll
    for (int t = 0; t < TT; t++) mu += y[t];
    mu *= 0.1f;
    float var = 0.f;
#pragma unroll
    for (int t = 0; t < TT; t++) { float d = y[t] - mu; var += d * d; }
    var *= 0.1f;
    float sc = ga * rsqrtf(var + 1e-5f);
#pragma unroll
    for (int t = 0; t < TT; t++)
        y[t] = fmaxf((y[t] - mu) * sc + be, 0.f);

    __syncwarp();
    *(float4*)&xh[ln][c][0] = make_float4(y[0], y[1], y[2], y[3]);
    *(float4*)&xh[ln][c][4] = make_float4(y[4], y[5], y[6], y[7]);
    *(float2*)&xh[ln][c][8] = make_float2(y[8], y[9]);
    __syncwarp();

    float o[TT];
#pragma unroll
    for (int t = 0; t < TT; t++) o[t] = 0.f;
#pragma unroll 4
    for (int cc = 0; cc < CH; cc++) {
        float g = gws[cc][c];
        float4 A = *(const float4*)&xh[ln][cc][0];
        float4 B = *(const float4*)&xh[ln][cc][4];
        float2 C2 = *(const float2*)&xh[ln][cc][8];
        o[0] = fmaf(g, A.x, o[0]); o[1] = fmaf(g, A.y, o[1]);
        o[2] = fmaf(g, A.z, o[2]); o[3] = fmaf(g, A.w, o[3]);
        o[4] = fmaf(g, B.x, o[4]); o[5] = fmaf(g, B.y, o[5]);
        o[6] = fmaf(g, B.z, o[6]); o[7] = fmaf(g, B.w, o[7]);
        o[8] = fmaf(g, C2.x, o[8]); o[9] = fmaf(g, C2.y, o[9]);
    }

    long gn = nodeBase + ln;
#pragma unroll
    for (int t = 0; t < TT; t++)
        hw_out[gn * TC + t * CH + c] = __float2half(o[t]);
}

// ---- one group of 4 edges: 4 full-width main passes + 1 full-width remainder
// pass (lane handles uint4[32+(lane&7)] of edge j0+(lane>>3)). Padding edges
// have nm=0 / src=0, so processing a full group is always safe. --------------
__device__ __forceinline__ void edge_group4(
    const __half* __restrict__ hw, int2 d, int j0, int lane, int lg, int lu,
    float acc0[8], float acc1[8])
{
#pragma unroll
    for (int u = 0; u < 4; u++) {
        int j = j0 + u;
        int   src = __shfl_sync(0xffffffff, d.x, j);
        float nm  = __int_as_float(__shfl_sync(0xffffffff, d.y, j));
        const uint4* p = (const uint4*)(hw + (size_t)src * TC);
        uint4 uu = __ldg(&p[lane]);
        float2 f0 = __half22float2(*(const __half2*)&uu.x);
        float2 f1 = __half22float2(*(const __half2*)&uu.y);
        float2 f2 = __half22float2(*(const __half2*)&uu.z);
        float2 f3 = __half22float2(*(const __half2*)&uu.w);
        acc0[0] = fmaf(nm, f0.x, acc0[0]); acc0[1] = fmaf(nm, f0.y, acc0[1]);
        acc0[2] = fmaf(nm, f1.x, acc0[2]); acc0[3] = fmaf(nm, f1.y, acc0[3]);
        acc0[4] = fmaf(nm, f2.x, acc0[4]); acc0[5] = fmaf(nm, f2.y, acc0[5]);
        acc0[6] = fmaf(nm, f3.x, acc0[6]); acc0[7] = fmaf(nm, f3.y, acc0[7]);
    }
    int jr = j0 + lg;
    int   srcr = __shfl_sync(0xffffffff, d.x, jr);
    float nmr  = __int_as_float(__shfl_sync(0xffffffff, d.y, jr));
    const uint4* pr = (const uint4*)(hw + (size_t)srcr * TC);
    uint4 vv = __ldg(&pr[32 + lu]);
    float2 g0 = __half22float2(*(const __half2*)&vv.x);
    float2 g1 = __half22float2(*(const __half2*)&vv.y);
    float2 g2 = __half22float2(*(const __half2*)&vv.z);
    float2 g3 = __half22float2(*(const __half2*)&vv.w);
    acc1[0] = fmaf(nmr, g0.x, acc1[0]); acc1[1] = fmaf(nmr, g0.y, acc1[1]);
    acc1[2] = fmaf(nmr, g1.x, acc1[2]); acc1[3] = fmaf(nmr, g1.y, acc1[3]);
    acc1[4] = fmaf(nmr, g2.x, acc1[4]); acc1[5] = fmaf(nmr, g2.y, acc1[5]);
    acc1[6] = fmaf(nmr, g3.x, acc1[6]); acc1[7] = fmaf(nmr, g3.y, acc1[7]);
}

// ---- butterfly-reduce acc1, add self-loop, bias/relu/clip -------------------
__device__ __forceinline__ void finish_node(
    const __half* __restrict__ hw, int node, int lane,
    const float* __restrict__ gb, float acc0[8], float acc1[8])
{
#pragma unroll
    for (int k = 0; k < 8; k++) {
        acc1[k] += __shfl_xor_sync(0xffffffff, acc1[k], 8);
        acc1[k] += __shfl_xor_sync(0xffffffff, acc1[k], 16);
    }
    float di = g_dinv[node];
    float w  = di * di;
    const uint4* p = (const uint4*)(hw + (size_t)node * TC);
    uint4 u = __ldg(&p[lane]);
    float2 f0 = __half22float2(*(const __half2*)&u.x);
    float2 f1 = __half22float2(*(const __half2*)&u.y);
    float2 f2 = __half22float2(*(const __half2*)&u.z);
    float2 f3 = __half22float2(*(const __half2*)&u.w);
    acc0[0] = fmaf(w, f0.x, acc0[0]); acc0[1] = fmaf(w, f0.y, acc0[1]);
    acc0[2] = fmaf(w, f1.x, acc0[2]); acc0[3] = fmaf(w, f1.y, acc0[3]);
    acc0[4] = fmaf(w, f2.x, acc0[4]); acc0[5] = fmaf(w, f2.y, acc0[5]);
    acc0[6] = fmaf(w, f3.x, acc0[6]); acc0[7] = fmaf(w, f3.y, acc0[7]);
    if (lane < 8) {
        uint4 v = __ldg(&p[32 + lane]);
        float2 g0 = __half22float2(*(const __half2*)&v.x);
        float2 g1 = __half22float2(*(const __half2*)&v.y);
        float2 g2 = __half22float2(*(const __half2*)&v.z);
        float2 g3 = __half22float2(*(const __half2*)&v.w);
        acc1[0] = fmaf(w, g0.x, acc1[0]); acc1[1] = fmaf(w, g0.y, acc1[1]);
        acc1[2] = fmaf(w, g1.x, acc1[2]); acc1[3] = fmaf(w, g1.y, acc1[3]);
        acc1[4] = fmaf(w, g2.x, acc1[4]); acc1[5] = fmaf(w, g2.y, acc1[5]);
        acc1[6] = fmaf(w, g3.x, acc1[6]); acc1[7] = fmaf(w, g3.y, acc1[7]);
    }
    int c0 = (8 * lane) & 31;
    float4 b0 = *(const float4*)&gb[c0];
    float4 b1 = *(const float4*)&gb[c0 + 4];
    acc0[0] = fminf(fmaxf(acc0[0] + b0.x, 0.f), 10.f);
    acc0[1] = fminf(fmaxf(acc0[1] + b0.y, 0.f), 10.f);
    acc0[2] = fminf(fmaxf(acc0[2] + b0.z, 0.f), 10.f);
    acc0[3] = fminf(fmaxf(acc0[3] + b0.w, 0.f), 10.f);
    acc0[4] = fminf(fmaxf(acc0[4] + b1.x, 0.f), 10.f);
    acc0[5] = fminf(fmaxf(acc0[5] + b1.y, 0.f), 10.f);
    acc0[6] = fminf(fmaxf(acc0[6] + b1.z, 0.f), 10.f);
    acc0[7] = fminf(fmaxf(acc0[7] + b1.w, 0.f), 10.f);
    if (lane < 8) {
        acc1[0] = fminf(fmaxf(acc1[0] + b0.x, 0.f), 10.f);
        acc1[1] = fminf(fmaxf(acc1[1] + b0.y, 0.f), 10.f);
        acc1[2] = fminf(fmaxf(acc1[2] + b0.z, 0.f), 10.f);
        acc1[3] = fminf(fmaxf(acc1[3] + b0.w, 0.f), 10.f);
        acc1[4] = fminf(fmaxf(acc1[4] + b1.x, 0.f), 10.f);
        acc1[5] = fminf(fmaxf(acc1[5] + b1.y, 0.f), 10.f);
        acc1[6] = fminf(fmaxf(acc1[6] + b1.z, 0.f), 10.f);
        acc1[7] = fminf(fmaxf(acc1[7] + b1.w, 0.f), 10.f);
    }
}

// ---- single-node gather with descriptor double-buffering --------------------
__device__ __forceinline__ void gather_node(
    const __half* __restrict__ hw, int node, int lane,
    const float* __restrict__ gb, float acc0[8], float acc1[8])
{
#pragma unroll
    for (int k = 0; k < 8; k++) { acc0[k] = 0.f; acc1[k] = 0.f; }

    int s = g_rowptr[node];
    int e = g_rowptr[node + 1];
    int lg = lane >> 3;
    int lu = lane & 7;

    int base = s;
    int2 d = make_int2(0, 0);
    if (base + lane < e) d = g_adj2[base + lane];

    while (base < e) {
        int nbase = base + 32;
        int2 dn = make_int2(0, 0);
        if (nbase + lane < e) dn = g_adj2[nbase + lane];   // prefetch next block
        int cnt = min(32, e - base);
#pragma unroll 2
        for (int j0 = 0; j0 < cnt; j0 += 4)
            edge_group4(hw, d, j0, lane, lg, lu, acc0, acc1);
        d = dn;
        base = nbase;
    }

    finish_node(hw, node, lane, gb, acc0, acc1);
}

// ------------ FUSED layer-1 aggregate + layer-2 conv/IN/relu/(h@gw) ----------
__global__ void __launch_bounds__(256, 5)
agg1_conv2_kernel(const __half* __restrict__ hw1,
                  const float* __restrict__ gb1,
                  const float* __restrict__ tw2, const float* __restrict__ tb2,
                  const float* __restrict__ gamma2, const float* __restrict__ beta2,
                  const float* __restrict__ gw2,
                  __half* __restrict__ hw2)
{
    const int TP = 12;
    __shared__ float s_xh[8][CH * TP];        // per-warp [c][t] tile (union x/h)
    __shared__ float4 tws4[CH][CH + 1];       // (w0,w1,w2,_), ODD row stride
    __shared__ float gws[CH][CH];

    int tid  = threadIdx.x;
    int warp = tid >> 5;
    int lane = tid & 31;
    int node = blockIdx.x * 8 + warp;

    for (int i = tid; i < CH * CH; i += 256) {
        int c  = i / CH;
        int ci = i % CH;
        const float* p = &tw2[(c * CH + ci) * 3];
        tws4[c][ci] = make_float4(p[0], p[1], p[2], 0.f);
    }
    for (int i = tid; i < CH * CH; i += 256)
        gws[i / CH][i % CH] = gw2[i];
    __syncthreads();

    float acc0[8], acc1[8];
    gather_node(hw1, node, lane, gb1, acc0, acc1);

    float* X = s_xh[warp];
#pragma unroll
    for (int k = 0; k < 8; k++) {
        int e = 8 * lane + k;
        X[(e & 31) * TP + (e >> 5)] = acc0[k];
    }
    if (lane < 8) {
#pragma unroll
        for (int k = 0; k < 8; k++) {
            int e = 256 + 8 * lane + k;
            X[(e & 31) * TP + (e >> 5)] = acc1[k];
        }
    }
    __syncwarp();

    int c = lane;
    float y[TT];
    float bias = tb2[c], ga = gamma2[c], be = beta2[c];
#pragma unroll
    for (int t = 0; t < TT; t++) y[t] = bias;
#pragma unroll 4
    for (int ci = 0; ci < CH; ci++) {
        float4 W = tws4[c][ci];
        float4 A = *(const float4*)&X[ci * TP + 0];
        float4 B = *(const float4*)&X[ci * TP + 4];
        float2 C2 = *(const float2*)&X[ci * TP + 8];
        float xv[10] = {A.x, A.y, A.z, A.w, B.x, B.y, B.z, B.w, C2.x, C2.y};
#pragma unroll
        for (int t = 0; t < TT; t++) {
            float a = y[t];
            if (t > 0)      a = fmaf(W.x, xv[t - 1], a);
            a = fmaf(W.y, xv[t], a);
            if (t < TT - 1) a = fmaf(W.z, xv[t + 1], a);
            y[t] = a;
        }
    }
#pragma unroll
    for (int t = 0; t < TT; t++) y[t] = fminf(fmaxf(y[t], -10.f), 10.f);

    float mu = 0.f;
#pragma unroll
    for (int t = 0; t < TT; t++) mu += y[t];
    mu *= 0.1f;
    float var = 0.f;
#pragma unroll
    for (int t = 0; t < TT; t++) { float d = y[t] - mu; var += d * d; }
    var *= 0.1f;
    float sc = ga * rsqrtf(var + 1e-5f);
#pragma unroll
    for (int t = 0; t < TT; t++)
        y[t] = fmaxf((y[t] - mu) * sc + be, 0.f);

    __syncwarp();
    *(float4*)&X[c * TP + 0] = make_float4(y[0], y[1], y[2], y[3]);
    *(float4*)&X[c * TP + 4] = make_float4(y[4], y[5], y[6], y[7]);
    *(float2*)&X[c * TP + 8] = make_float2(y[8], y[9]);
    __syncwarp();

    float o[TT];
#pragma unroll
    for (int t = 0; t < TT; t++) o[t] = 0.f;
#pragma unroll 4
    for (int cc = 0; cc < CH; cc++) {
        float g = gws[cc][c];
        float4 A = *(const float4*)&X[cc * TP + 0];
        float4 B = *(const float4*)&X[cc * TP + 4];
        float2 C2 = *(const float2*)&X[cc * TP + 8];
        o[0] = fmaf(g, A.x, o[0]); o[1] = fmaf(g, A.y, o[1]);
        o[2] = fmaf(g, A.z, o[2]); o[3] = fmaf(g, A.w, o[3]);
        o[4] = fmaf(g, B.x, o[4]); o[5] = fmaf(g, B.y, o[5]);
        o[6] = fmaf(g, B.z, o[6]); o[7] = fmaf(g, B.w, o[7]);
        o[8] = fmaf(g, C2.x, o[8]); o[9] = fmaf(g, C2.y, o[9]);
    }

    long gn = node;
#pragma unroll
    for (int t = 0; t < TT; t++)
        hw2[gn * TC + t * CH + c] = __float2half(o[t]);
}

// ------------ layer-2 aggregate fused with mean-over-T + output linear -------
__global__ void __launch_bounds__(256, 5)
agg2_head_kernel(const __half* __restrict__ hw,
                 const float* __restrict__ gb,
                 float* __restrict__ out,
                 const float* __restrict__ ow,
                 const float* __restrict__ ob)
{
    __shared__ float s_feat[8][TC];
    __shared__ float s_m[8][CH];

    int warp = threadIdx.x >> 5;
    int lane = threadIdx.x & 31;
    int node = blockIdx.x * 8 + warp;

    float acc0[8], acc1[8];
    gather_node(hw, node, lane, gb, acc0, acc1);

    *(float4*)&s_feat[warp][8 * lane]     = make_float4(acc0[0], acc0[1], acc0[2], acc0[3]);
    *(float4*)&s_feat[warp][8 * lane + 4] = make_float4(acc0[4], acc0[5], acc0[6], acc0[7]);
    if (lane < 8) {
        *(float4*)&s_feat[warp][256 + 8 * lane]     = make_float4(acc1[0], acc1[1], acc1[2], acc1[3]);
        *(float4*)&s_feat[warp][256 + 8 * lane + 4] = make_float4(acc1[4], acc1[5], acc1[6], acc1[7]);
    }
    __syncwarp();
    float m = 0.f;
#pragma unroll
    for (int t = 0; t < TT; t++) m += s_feat[warp][t * CH + lane];
    s_m[warp][lane] = m * 0.1f;
    __syncwarp();
    if (lane < COUT) {
        float o = ob[lane];
#pragma unroll
        for (int cc = 0; cc < CH; cc++)
            o = fmaf(s_m[warp][cc], __ldg(&ow[cc * COUT + lane]), o);
        out[(size_t)node * COUT + lane] = o;
    }
}

// ---------------------------------------------------------------------------
extern "C" void kernel_launch(void* const* d_in, const int* in_sizes, int n_in,
                              void* d_out, int out_size)
{
    const float* x   = (const float*)d_in[0];
    const int*   ei  = (const int*)  d_in[1];   // [2, E]
    const float* ew  = (const float*)d_in[2];
    const float* l1_tw    = (const float*)d_in[3];
    const float* l1_tb    = (const float*)d_in[4];
    const float* l1_gw    = (const float*)d_in[5];
    const float* l1_gb    = (const float*)d_in[6];
    const float* l1_gamma = (const float*)d_in[7];
    const float* l1_beta  = (const float*)d_in[8];
    const float* l2_tw    = (const float*)d_in[9];
    const float* l2_tb    = (const float*)d_in[10];
    const float* l2_gw    = (const float*)d_in[11];
    const float* l2_gb    = (const float*)d_in[12];
    const float* l2_gamma = (const float*)d_in[13];
    const float* l2_beta  = (const float*)d_in[14];
    const float* out_w    = (const float*)d_in[15];
    const float* out_b    = (const float*)d_in[16];

    const int* e_row = ei;        // sources
    const int* e_col = ei + EE;   // destinations

    __half* hw1_ptr; cudaGetSymbolAddress((void**)&hw1_ptr, g_hw1);
    __half* hw2_ptr; cudaGetSymbolAddress((void**)&hw2_ptr, g_hw2);
    float* ewn_ptr;  cudaGetSymbolAddress((void**)&ewn_ptr, g_ewn);

    // One-time host-side resources (no device memory involved).
    static cudaStream_t s2 = nullptr;
    static cudaEvent_t evA = nullptr, evB = nullptr;
    if (s2 == nullptr) {
        cudaStreamCreateWithFlags(&s2, cudaStreamNonBlocking);
        cudaEventCreateWithFlags(&evA, cudaEventDisableTiming);
        cudaEventCreateWithFlags(&evB, cudaEventDisableTiming);
    }

    // fork: graph-prep chain on s2, conv1 on the origin stream
    cudaEventRecord(evA, 0);
    cudaStreamWaitEvent(s2, evA, 0);

    expdeg_scan_kernel<<<NBLK2, 1024, 0, s2>>>(
        (const float4*)ew, (float4*)ewn_ptr, (const int4*)e_col);
    fill_kernel<<<NBLK, 256, 0, s2>>>(
        (const int4*)e_row, (const int4*)e_col, (const float4*)ewn_ptr);
    cudaEventRecord(evB, s2);

    conv1_kernel<<<NN / 8, 256>>>(
        x, l1_tw, l1_tb, l1_gamma, l1_beta, l1_gw, hw1_ptr);

    // join: aggregates need both conv1 output and the CSR
    cudaStreamWaitEvent(0, evB, 0);

    agg1_conv2_kernel<<<NN / 8, 256>>>(
        hw1_ptr, l1_gb, l2_tw, l2_tb, l2_gamma, l2_beta, l2_gw, hw2_ptr);
    agg2_head_kernel<<<NN / 8, 256>>>(hw2_ptr, l2_gb, (float*)d_out, out_w, out_b);
}

// round 15
// speedup vs baseline: 1.1852x; 1.0645x over previous
#include <cuda_runtime.h>
#include <cuda_fp16.h>
#include <math.h>

// ---------------------------------------------------------------------------
// STGCN: 2x (temporal conv -> clip -> InstanceNorm -> ReLU -> GCN) -> linear -> mean_T
// T=10, N=10000, E=320000, C_IN=16, C_HID=32, C_OUT=16
// Pipeline: [conv1] || [expdeg_scan -> fill]  ->  agg1+conv2  ->  agg2+head
// Gather runs in fp16 (HFMA2) with norm pre-scaled x4096: softmax over 320k
// edges bounds norm <= 8.5e-6, so edge sums are ~1e-4 of the output and fp16
// accumulation error is negligible; scaling keeps values out of subnormals.
// ---------------------------------------------------------------------------

#define TT 10
#define NN 10000
#define EE 320000
#define CH 32
#define COUT 16
#define TC (TT * CH)        // 320 features per node
#define E4 (EE / 4)         // 80000
#define NBLK ((E4 + 255) / 256)      // 313  (fill grid)
#define NBLK2 ((E4 + 1023) / 1024)   // 79   (expdeg grid)
#define NORM_SCALE 4096.f
#define NORM_INV   (1.f / 4096.f)

// ------------------------- device scratch (no allocs allowed) ---------------
__device__ __half g_hw1[NN * TC];    // layer-1 h@gw fp16, [node][t*32+c]
__device__ __half g_hw2[NN * TC];    // layer-2 h@gw fp16, [node][t*32+c]
__device__ float  g_ewn [EE];        // raw exp(w)
__device__ int2   g_adj2[EE];        // CSR: {src, half2(norm*4096, norm*4096)}
__device__ int    g_rowptr[NN + 1];
__device__ int    g_cnt [NN];        // re-zeroed by fill tail
__device__ int    g_fill[NN];        // write cursor (init = rowptr by scan)
__device__ float  g_deg [NN];        // re-zeroed by fill tail
__device__ float  g_dinv[NN];
__device__ float  g_partial[NBLK2];
__device__ float  g_inv_sumexp;
__device__ unsigned int g_done;      // last-block ticket (reset each pass)

// ---- fused one-kernel prep: exp(w) + partial sums + deg/cnt atomics; the
//      LAST block then computes inv_sumexp, rowptr scan (+fill cursor), dinv --
__global__ void __launch_bounds__(1024)
expdeg_scan_kernel(const float4* __restrict__ w,
                   float4* __restrict__ ewn4,
                   const int4* __restrict__ col4)
{
    __shared__ float sm[1024];
    __shared__ int   ssum[1024];
    __shared__ int   s_last;

    int tid = threadIdx.x;
    int i = blockIdx.x * 1024 + tid;
    float s = 0.f;
    if (i < E4) {
        float4 a = w[i];
        float4 e;
        e.x = expf(a.x); e.y = expf(a.y); e.z = expf(a.z); e.w = expf(a.w);
        ewn4[i] = e;
        s = e.x + e.y + e.z + e.w;
        int4 c = col4[i];
        atomicAdd(&g_deg[c.x], e.x); atomicAdd(&g_cnt[c.x], 1);
        atomicAdd(&g_deg[c.y], e.y); atomicAdd(&g_cnt[c.y], 1);
        atomicAdd(&g_deg[c.z], e.z); atomicAdd(&g_cnt[c.z], 1);
        atomicAdd(&g_deg[c.w], e.w); atomicAdd(&g_cnt[c.w], 1);
    }
    sm[tid] = s;
    __syncthreads();
    for (int o = 512; o > 0; o >>= 1) {
        if (tid < o) sm[tid] += sm[tid + o];
        __syncthreads();
    }
    if (tid == 0) g_partial[blockIdx.x] = sm[0];
    __threadfence();
    if (tid == 0) s_last = (atomicAdd(&g_done, 1) == gridDim.x - 1);
    __syncthreads();
    if (!s_last) return;

    // ---- last block: finish everything ----
    if (tid == 0) g_done = 0;       // reset ticket for next call
    __threadfence();

    sm[tid] = (tid < NBLK2) ? g_partial[tid] : 0.f;
    __syncthreads();
    for (int o = 512; o > 0; o >>= 1) {
        if (tid < o) sm[tid] += sm[tid + o];
        __syncthreads();
    }
    float inv = 1.f / sm[0];
    if (tid == 0) g_inv_sumexp = inv;

    const int CHK = (NN + 1023) / 1024;   // 10
    int local[CHK];
    int base = tid * CHK;
    int acc = 0;
#pragma unroll
    for (int k = 0; k < CHK; k++) {
        int idx = base + k;
        local[k] = (idx < NN) ? g_cnt[idx] : 0;
        acc += local[k];
    }
    ssum[tid] = acc;
    __syncthreads();
    for (int off = 1; off < 1024; off <<= 1) {
        int v = (tid >= off) ? ssum[tid - off] : 0;
        __syncthreads();
        ssum[tid] += v;
        __syncthreads();
    }
    int ex = ssum[tid] - acc;
#pragma unroll
    for (int k = 0; k < CHK; k++) {
        int idx = base + k;
        if (idx < NN) { g_rowptr[idx] = ex; g_fill[idx] = ex; }
        ex += local[k];
    }
    if (tid == 1023) g_rowptr[NN] = ssum[1023];
    for (int idx = tid; idx < NN; idx += 1024)
        g_dinv[idx] = rsqrtf(inv * g_deg[idx] + 1.0f);
}

// ---- CSR fill, 4 edges/thread; norm stored as duplicated half2 (x4096) ------
__device__ __forceinline__ int pack_norm_h2(float n) {
    unsigned short h = __half_as_ushort(__float2half_rn(n * NORM_SCALE));
    unsigned int p = (unsigned int)h | ((unsigned int)h << 16);
    return (int)p;
}

__global__ void fill_kernel(const int4* __restrict__ row4, const int4* __restrict__ col4,
                            const float4* __restrict__ ewn4) {
    int i = blockIdx.x * blockDim.x + threadIdx.x;
    if (i < E4) {
        int4   c = col4[i];
        int4   r = row4[i];
        float4 w = ewn4[i];
        float inv = g_inv_sumexp;
        int p0 = atomicAdd(&g_fill[c.x], 1);
        int p1 = atomicAdd(&g_fill[c.y], 1);
        int p2 = atomicAdd(&g_fill[c.z], 1);
        int p3 = atomicAdd(&g_fill[c.w], 1);
        float n0 = g_dinv[r.x] * (w.x * inv) * g_dinv[c.x];
        float n1 = g_dinv[r.y] * (w.y * inv) * g_dinv[c.y];
        float n2 = g_dinv[r.z] * (w.z * inv) * g_dinv[c.z];
        float n3 = g_dinv[r.w] * (w.w * inv) * g_dinv[c.w];
        g_adj2[p0] = make_int2(r.x, pack_norm_h2(n0));
        g_adj2[p1] = make_int2(r.y, pack_norm_h2(n1));
        g_adj2[p2] = make_int2(r.z, pack_norm_h2(n2));
        g_adj2[p3] = make_int2(r.w, pack_norm_h2(n3));
    }
    if (i < NN) { g_cnt[i] = 0; g_deg[i] = 0.f; }
}

// ------------------- layer-1: temporal conv + IN + relu + (h @ gw) ----------
__global__ void __launch_bounds__(256)
conv1_kernel(const float* __restrict__ x,
             const float* __restrict__ tw, const float* __restrict__ tb,
             const float* __restrict__ gamma, const float* __restrict__ beta,
             const float* __restrict__ gw, __half* __restrict__ hw_out)
{
    const int CIN = 16;
    const int NPB = 8;
    const int TP = 12;
    __shared__ float xh[NPB][CH][TP];      // union: x rows [0,CIN), then h rows [0,32)
    __shared__ float4 tws4[CH][CIN + 1];   // (w0,w1,w2,_), ODD row stride: no conflicts
    __shared__ float gws[CH][CH];

    int tid = threadIdx.x;
    int nodeBase = blockIdx.x * NPB;

    for (int i = tid; i < NPB * TT * CIN; i += 256) {
        int ln = i / (TT * CIN);
        int r  = i % (TT * CIN);
        int t  = r / CIN;
        int ci = r % CIN;
        long gn = nodeBase + ln;
        xh[ln][ci][t] = x[(long)t * (NN * CIN) + gn * CIN + ci];
    }
    for (int i = tid; i < CH * CIN; i += 256) {
        int c  = i / CIN;
        int ci = i % CIN;
        const float* p = &tw[(c * CIN + ci) * 3];
        tws4[c][ci] = make_float4(p[0], p[1], p[2], 0.f);
    }
    for (int i = tid; i < CH * CH; i += 256)
        gws[i / CH][i % CH] = gw[i];
    __syncthreads();

    int ln = tid >> 5;
    int c  = tid & 31;
    float bias = tb[c], ga = gamma[c], be = beta[c];

    float y[TT];
#pragma unroll
    for (int t = 0; t < TT; t++) y[t] = bias;

#pragma unroll 4
    for (int ci = 0; ci < CIN; ci++) {
        float4 W = tws4[c][ci];
        float4 A = *(const float4*)&xh[ln][ci][0];
        float4 B = *(const float4*)&xh[ln][ci][4];
        float2 C2 = *(const float2*)&xh[ln][ci][8];
        float xv[10] = {A.x, A.y, A.z, A.w, B.x, B.y, B.z, B.w, C2.x, C2.y};
#pragma unroll
        for (int t = 0; t < TT; t++) {
            float a = y[t];
            if (t > 0)      a = fmaf(W.x, xv[t - 1], a);
            a = fmaf(W.y, xv[t], a);
            if (t < TT - 1) a = fmaf(W.z, xv[t + 1], a);
            y[t] = a;
        }
    }
#pragma unroll
    for (int t = 0; t < TT; t++) y[t] = fminf(fmaxf(y[t], -10.f), 10.f);

    float mu = 0.f;
#pragma unroll
    for (int t = 0; t < TT; t++) mu += y[t];
    mu *= 0.1f;
    float var = 0.f;
#pragma unroll
    for (int t = 0; t < TT; t++) { float d = y[t] - mu; var += d * d; }
    var *= 0.1f;
    float sc = ga * rsqrtf(var + 1e-5f);
#pragma unroll
    for (int t = 0; t < TT; t++)
        y[t] = fmaxf((y[t] - mu) * sc + be, 0.f);

    __syncwarp();
    *(float4*)&xh[ln][c][0] = make_float4(y[0], y[1], y[2], y[3]);
    *(float4*)&xh[ln][c][4] = make_float4(y[4], y[5], y[6], y[7]);
    *(float2*)&xh[ln][c][8] = make_float2(y[8], y[9]);
    __syncwarp();

    float o[TT];
#pragma unroll
    for (int t = 0; t < TT; t++) o[t] = 0.f;
#pragma unroll 4
    for (int cc = 0; cc < CH; cc++) {
        float g = gws[cc][c];
        float4 A = *(const float4*)&xh[ln][cc][0];
        float4 B = *(const float4*)&xh[ln][cc][4];
        float2 C2 = *(const float2*)&xh[ln][cc][8];
        o[0] = fmaf(g, A.x, o[0]); o[1] = fmaf(g, A.y, o[1]);
        o[2] = fmaf(g, A.z, o[2]); o[3] = fmaf(g, A.w, o[3]);
        o[4] = fmaf(g, B.x, o[4]); o[5] = fmaf(g, B.y, o[5]);
        o[6] = fmaf(g, B.z, o[6]); o[7] = fmaf(g, B.w, o[7]);
        o[8] = fmaf(g, C2.x, o[8]); o[9] = fmaf(g, C2.y, o[9]);
    }

    long gn = nodeBase + ln;
#pragma unroll
    for (int t = 0; t < TT; t++)
        hw_out[gn * TC + t * CH + c] = __float2half(o[t]);
}

// ---- one group of 4 edges, fp16 accumulation (HFMA2). Padding edges have
// nm=0 / src=0, so processing a full group is always safe. -------------------
__device__ __forceinline__ void edge_group4(
    const __half* __restrict__ hw, int2 d, int j0, int lane, int lg, int lu,
    __half2 hacc0[4], __half2 hacc1[4])
{
#pragma unroll
    for (int u = 0; u < 4; u++) {
        int j = j0 + u;
        int src = __shfl_sync(0xffffffff, d.x, j);
        int nmb = __shfl_sync(0xffffffff, d.y, j);
        __half2 nm2 = *reinterpret_cast<const __half2*>(&nmb);
        const uint4* p = (const uint4*)(hw + (size_t)src * TC);
        uint4 uu = __ldg(&p[lane]);
        hacc0[0] = __hfma2(nm2, *(const __half2*)&uu.x, hacc0[0]);
        hacc0[1] = __hfma2(nm2, *(const __half2*)&uu.y, hacc0[1]);
        hacc0[2] = __hfma2(nm2, *(const __half2*)&uu.z, hacc0[2]);
        hacc0[3] = __hfma2(nm2, *(const __half2*)&uu.w, hacc0[3]);
    }
    int jr = j0 + lg;
    int srcr = __shfl_sync(0xffffffff, d.x, jr);
    int nmbr = __shfl_sync(0xffffffff, d.y, jr);
    __half2 nm2r = *reinterpret_cast<const __half2*>(&nmbr);
    const uint4* pr = (const uint4*)(hw + (size_t)srcr * TC);
    uint4 vv = __ldg(&pr[32 + lu]);
    hacc1[0] = __hfma2(nm2r, *(const __half2*)&vv.x, hacc1[0]);
    hacc1[1] = __hfma2(nm2r, *(const __half2*)&vv.y, hacc1[1]);
    hacc1[2] = __hfma2(nm2r, *(const __half2*)&vv.z, hacc1[2]);
    hacc1[3] = __hfma2(nm2r, *(const __half2*)&vv.w, hacc1[3]);
}

// ---- butterfly-reduce acc1, add self-loop (fp32), bias/relu/clip ------------
__device__ __forceinline__ void finish_node(
    const __half* __restrict__ hw, int node, int lane,
    const float* __restrict__ gb, float acc0[8], float acc1[8])
{
#pragma unroll
    for (int k = 0; k < 8; k++) {
        acc1[k] += __shfl_xor_sync(0xffffffff, acc1[k], 8);
        acc1[k] += __shfl_xor_sync(0xffffffff, acc1[k], 16);
    }
    float di = g_dinv[node];
    float w  = di * di;
    const uint4* p = (const uint4*)(hw + (size_t)node * TC);
    uint4 u = __ldg(&p[lane]);
    float2 f0 = __half22float2(*(const __half2*)&u.x);
    float2 f1 = __half22float2(*(const __half2*)&u.y);
    float2 f2 = __half22float2(*(const __half2*)&u.z);
    float2 f3 = __half22float2(*(const __half2*)&u.w);
    acc0[0] = fmaf(w, f0.x, acc0[0]); acc0[1] = fmaf(w, f0.y, acc0[1]);
    acc0[2] = fmaf(w, f1.x, acc0[2]); acc0[3] = fmaf(w, f1.y, acc0[3]);
    acc0[4] = fmaf(w, f2.x, acc0[4]); acc0[5] = fmaf(w, f2.y, acc0[5]);
    acc0[6] = fmaf(w, f3.x, acc0[6]); acc0[7] = fmaf(w, f3.y, acc0[7]);
    if (lane < 8) {
        uint4 v = __ldg(&p[32 + lane]);
        float2 g0 = __half22float2(*(const __half2*)&v.x);
        float2 g1 = __half22float2(*(const __half2*)&v.y);
        float2 g2 = __half22float2(*(const __half2*)&v.z);
        float2 g3 = __half22float2(*(const __half2*)&v.w);
        acc1[0] = fmaf(w, g0.x, acc1[0]); acc1[1] = fmaf(w, g0.y, acc1[1]);
        acc1[2] = fmaf(w, g1.x, acc1[2]); acc1[3] = fmaf(w, g1.y, acc1[3]);
        acc1[4] = fmaf(w, g2.x, acc1[4]); acc1[5] = fmaf(w, g2.y, acc1[5]);
        acc1[6] = fmaf(w, g3.x, acc1[6]); acc1[7] = fmaf(w, g3.y, acc1[7]);
    }
    int c0 = (8 * lane) & 31;
    float4 b0 = *(const float4*)&gb[c0];
    float4 b1 = *(const float4*)&gb[c0 + 4];
    acc0[0] = fminf(fmaxf(acc0[0] + b0.x, 0.f), 10.f);
    acc0[1] = fminf(fmaxf(acc0[1] + b0.y, 0.f), 10.f);
    acc0[2] = fminf(fmaxf(acc0[2] + b0.z, 0.f), 10.f);
    acc0[3] = fminf(fmaxf(acc0[3] + b0.w, 0.f), 10.f);
    acc0[4] = fminf(fmaxf(acc0[4] + b1.x, 0.f), 10.f);
    acc0[5] = fminf(fmaxf(acc0[5] + b1.y, 0.f), 10.f);
    acc0[6] = fminf(fmaxf(acc0[6] + b1.z, 0.f), 10.f);
    acc0[7] = fminf(fmaxf(acc0[7] + b1.w, 0.f), 10.f);
    if (lane < 8) {
        acc1[0] = fminf(fmaxf(acc1[0] + b0.x, 0.f), 10.f);
        acc1[1] = fminf(fmaxf(acc1[1] + b0.y, 0.f), 10.f);
        acc1[2] = fminf(fmaxf(acc1[2] + b0.z, 0.f), 10.f);
        acc1[3] = fminf(fmaxf(acc1[3] + b0.w, 0.f), 10.f);
        acc1[4] = fminf(fmaxf(acc1[4] + b1.x, 0.f), 10.f);
        acc1[5] = fminf(fmaxf(acc1[5] + b1.y, 0.f), 10.f);
        acc1[6] = fminf(fmaxf(acc1[6] + b1.z, 0.f), 10.f);
        acc1[7] = fminf(fmaxf(acc1[7] + b1.w, 0.f), 10.f);
    }
}

// ---- single-node gather: fp16 edge accumulation + descriptor prefetch -------
__device__ __forceinline__ void gather_node(
    const __half* __restrict__ hw, int node, int lane,
    const float* __restrict__ gb, float acc0[8], float acc1[8])
{
    __half2 z = __float2half2_rn(0.f);
    __half2 h0[4] = {z, z, z, z};
    __half2 h1[4] = {z, z, z, z};

    int s = g_rowptr[node];
    int e = g_rowptr[node + 1];
    int lg = lane >> 3;
    int lu = lane & 7;

    int base = s;
    int2 d = make_int2(0, 0);
    if (base + lane < e) d = g_adj2[base + lane];

    while (base < e) {
        int nbase = base + 32;
        int2 dn = make_int2(0, 0);
        if (nbase + lane < e) dn = g_adj2[nbase + lane];   // prefetch next block
        int cnt = min(32, e - base);
#pragma unroll 2
        for (int j0 = 0; j0 < cnt; j0 += 4)
            edge_group4(hw, d, j0, lane, lg, lu, h0, h1);
        d = dn;
        base = nbase;
    }

    // flush fp16 accumulators to fp32 (undo x4096 scale)
#pragma unroll
    for (int k = 0; k < 4; k++) {
        float2 f = __half22float2(h0[k]);
        acc0[2 * k]     = f.x * NORM_INV;
        acc0[2 * k + 1] = f.y * NORM_INV;
        float2 g = __half22float2(h1[k]);
        acc1[2 * k]     = g.x * NORM_INV;
        acc1[2 * k + 1] = g.y * NORM_INV;
    }

    finish_node(hw, node, lane, gb, acc0, acc1);
}

// ------------ FUSED layer-1 aggregate + layer-2 conv/IN/relu/(h@gw) ----------
__global__ void __launch_bounds__(256, 5)
agg1_conv2_kernel(const __half* __restrict__ hw1,
                  const float* __restrict__ gb1,
                  const float* __restrict__ tw2, const float* __restrict__ tb2,
                  const float* __restrict__ gamma2, const float* __restrict__ beta2,
                  const float* __restrict__ gw2,
                  __half* __restrict__ hw2)
{
    const int TP = 12;
    __shared__ float s_xh[8][CH * TP];        // per-warp [c][t] tile (union x/h)
    __shared__ float4 tws4[CH][CH + 1];       // (w0,w1,w2,_), ODD row stride
    __shared__ float gws[CH][CH];

    int tid  = threadIdx.x;
    int warp = tid >> 5;
    int lane = tid & 31;
    int node = blockIdx.x * 8 + warp;

    for (int i = tid; i < CH * CH; i += 256) {
        int c  = i / CH;
        int ci = i % CH;
        const float* p = &tw2[(c * CH + ci) * 3];
        tws4[c][ci] = make_float4(p[0], p[1], p[2], 0.f);
    }
    for (int i = tid; i < CH * CH; i += 256)
        gws[i / CH][i % CH] = gw2[i];
    __syncthreads();

    float acc0[8], acc1[8];
    gather_node(hw1, node, lane, gb1, acc0, acc1);

    float* X = s_xh[warp];
#pragma unroll
    for (int k = 0; k < 8; k++) {
        int e = 8 * lane + k;
        X[(e & 31) * TP + (e >> 5)] = acc0[k];
    }
    if (lane < 8) {
#pragma unroll
        for (int k = 0; k < 8; k++) {
            int e = 256 + 8 * lane + k;
            X[(e & 31) * TP + (e >> 5)] = acc1[k];
        }
    }
    __syncwarp();

    int c = lane;
    float y[TT];
    float bias = tb2[c], ga = gamma2[c], be = beta2[c];
#pragma unroll
    for (int t = 0; t < TT; t++) y[t] = bias;
#pragma unroll 4
    for (int ci = 0; ci < CH; ci++) {
        float4 W = tws4[c][ci];
        float4 A = *(const float4*)&X[ci * TP + 0];
        float4 B = *(const float4*)&X[ci * TP + 4];
        float2 C2 = *(const float2*)&X[ci * TP + 8];
        float xv[10] = {A.x, A.y, A.z, A.w, B.x, B.y, B.z, B.w, C2.x, C2.y};
#pragma unroll
        for (int t = 0; t < TT; t++) {
            float a = y[t];
            if (t > 0)      a = fmaf(W.x, xv[t - 1], a);
            a = fmaf(W.y, xv[t], a);
            if (t < TT - 1) a = fmaf(W.z, xv[t + 1], a);
            y[t] = a;
        }
    }
#pragma unroll
    for (int t = 0; t < TT; t++) y[t] = fminf(fmaxf(y[t], -10.f), 10.f);

    float mu = 0.f;
#pragma unroll
    for (int t = 0; t < TT; t++) mu += y[t];
    mu *= 0.1f;
    float var = 0.f;
#pragma unroll
    for (int t = 0; t < TT; t++) { float d = y[t] - mu; var += d * d; }
    var *= 0.1f;
    float sc = ga * rsqrtf(var + 1e-5f);
#pragma unroll
    for (int t = 0; t < TT; t++)
        y[t] = fmaxf((y[t] - mu) * sc + be, 0.f);

    __syncwarp();
    *(float4*)&X[c * TP + 0] = make_float4(y[0], y[1], y[2], y[3]);
    *(float4*)&X[c * TP + 4] = make_float4(y[4], y[5], y[6], y[7]);
    *(float2*)&X[c * TP + 8] = make_float2(y[8], y[9]);
    __syncwarp();

    float o[TT];
#pragma unroll
    for (int t = 0; t < TT; t++) o[t] = 0.f;
#pragma unroll 4
    for (int cc = 0; cc < CH; cc++) {
        float g = gws[cc][c];
        float4 A = *(const float4*)&X[cc * TP + 0];
        float4 B = *(const float4*)&X[cc * TP + 4];
        float2 C2 = *(const float2*)&X[cc * TP + 8];
        o[0] = fmaf(g, A.x, o[0]); o[1] = fmaf(g, A.y, o[1]);
        o[2] = fmaf(g, A.z, o[2]); o[3] = fmaf(g, A.w, o[3]);
        o[4] = fmaf(g, B.x, o[4]); o[5] = fmaf(g, B.y, o[5]);
        o[6] = fmaf(g, B.z, o[6]); o[7] = fmaf(g, B.w, o[7]);
        o[8] = fmaf(g, C2.x, o[8]); o[9] = fmaf(g, C2.y, o[9]);
    }

    long gn = node;
#pragma unroll
    for (int t = 0; t < TT; t++)
        hw2[gn * TC + t * CH + c] = __float2half(o[t]);
}

// ------------ layer-2 aggregate fused with mean-over-T + output linear -------
__global__ void __launch_bounds__(256, 5)
agg2_head_kernel(const __half* __restrict__ hw,
                 const float* __restrict__ gb,
                 float* __restrict__ out,
                 const float* __restrict__ ow,
                 const float* __restrict__ ob)
{
    __shared__ float s_feat[8][TC];
    __shared__ float s_m[8][CH];

    int warp = threadIdx.x >> 5;
    int lane = threadIdx.x & 31;
    int node = blockIdx.x * 8 + warp;

    float acc0[8], acc1[8];
    gather_node(hw, node, lane, gb, acc0, acc1);

    *(float4*)&s_feat[warp][8 * lane]     = make_float4(acc0[0], acc0[1], acc0[2], acc0[3]);
    *(float4*)&s_feat[warp][8 * lane + 4] = make_float4(acc0[4], acc0[5], acc0[6], acc0[7]);
    if (lane < 8) {
        *(float4*)&s_feat[warp][256 + 8 * lane]     = make_float4(acc1[0], acc1[1], acc1[2], acc1[3]);
        *(float4*)&s_feat[warp][256 + 8 * lane + 4] = make_float4(acc1[4], acc1[5], acc1[6], acc1[7]);
    }
    __syncwarp();
    float m = 0.f;
#pragma unroll
    for (int t = 0; t < TT; t++) m += s_feat[warp][t * CH + lane];
    s_m[warp][lane] = m * 0.1f;
    __syncwarp();
    if (lane < COUT) {
        float o = ob[lane];
#pragma unroll
        for (int cc = 0; cc < CH; cc++)
            o = fmaf(s_m[warp][cc], __ldg(&ow[cc * COUT + lane]), o);
        out[(size_t)node * COUT + lane] = o;
    }
}

// ---------------------------------------------------------------------------
extern "C" void kernel_launch(void* const* d_in, const int* in_sizes, int n_in,
                              void* d_out, int out_size)
{
    const float* x   = (const float*)d_in[0];
    const int*   ei  = (const int*)  d_in[1];   // [2, E]
    const float* ew  = (const float*)d_in[2];
    const float* l1_tw    = (const float*)d_in[3];
    const float* l1_tb    = (const float*)d_in[4];
    const float* l1_gw    = (const float*)d_in[5];
    const float* l1_gb    = (const float*)d_in[6];
    const float* l1_gamma = (const float*)d_in[7];
    const float* l1_beta  = (const float*)d_in[8];
    const float* l2_tw    = (const float*)d_in[9];
    const float* l2_tb    = (const float*)d_in[10];
    const float* l2_gw    = (const float*)d_in[11];
    const float* l2_gb    = (const float*)d_in[12];
    const float* l2_gamma = (const float*)d_in[13];
    const float* l2_beta  = (const float*)d_in[14];
    const float* out_w    = (const float*)d_in[15];
    const float* out_b    = (const float*)d_in[16];

    const int* e_row = ei;        // sources
    const int* e_col = ei + EE;   // destinations

    __half* hw1_ptr; cudaGetSymbolAddress((void**)&hw1_ptr, g_hw1);
    __half* hw2_ptr; cudaGetSymbolAddress((void**)&hw2_ptr, g_hw2);
    float* ewn_ptr;  cudaGetSymbolAddress((void**)&ewn_ptr, g_ewn);

    // One-time host-side resources (no device memory involved).
    static cudaStream_t s2 = nullptr;
    static cudaEvent_t evA = nullptr, evB = nullptr;
    if (s2 == nullptr) {
        cudaStreamCreateWithFlags(&s2, cudaStreamNonBlocking);
        cudaEventCreateWithFlags(&evA, cudaEventDisableTiming);
        cudaEventCreateWithFlags(&evB, cudaEventDisableTiming);
    }

    // fork: graph-prep chain on s2, conv1 on the origin stream
    cudaEventRecord(evA, 0);
    cudaStreamWaitEvent(s2, evA, 0);

    expdeg_scan_kernel<<<NBLK2, 1024, 0, s2>>>(
        (const float4*)ew, (float4*)ewn_ptr, (const int4*)e_col);
    fill_kernel<<<NBLK, 256, 0, s2>>>(
        (const int4*)e_row, (const int4*)e_col, (const float4*)ewn_ptr);
    cudaEventRecord(evB, s2);

    conv1_kernel<<<NN / 8, 256>>>(
        x, l1_tw, l1_tb, l1_gamma, l1_beta, l1_gw, hw1_ptr);

    // join: aggregates need both conv1 output and the CSR
    cudaStreamWaitEvent(0, evB, 0);

    agg1_conv2_kernel<<<NN / 8, 256>>>(
        hw1_ptr, l1_gb, l2_tw, l2_tb, l2_gamma, l2_beta, l2_gw, hw2_ptr);
    agg2_head_kernel<<<NN / 8, 256>>>(hw2_ptr, l2_gb, (float*)d_out, out_w, out_b);
}